// round 5
// baseline (speedup 1.0000x reference)
#include <cuda_runtime.h>
#include <cuda_bf16.h>

#define BB 256
#define SS 8192
#define NPOS (BB * SS)           // 2,097,152 positions
#define NGRP (NPOS / 4)          // 524,288 groups of 4 positions
#define NBLK 2048                // NGRP / 256
#define IGNORE_LBL (-100)

// Per-block partials: fixed slots, overwritten every launch -> no zeroing, no atomics.
__device__ float    d_pa[NBLK];   // aspect focal partial sums
__device__ float    d_po[NBLK];   // opinion focal partial sums
__device__ float    d_pb[NBLK];   // boundary bce partial sums
__device__ unsigned d_ca[NBLK];   // aspect valid counts
__device__ unsigned d_co[NBLK];   // opinion valid counts

__device__ __forceinline__ float warp_sum_f(float v) {
    #pragma unroll
    for (int o = 16; o > 0; o >>= 1) v += __shfl_down_sync(0xffffffffu, v, o);
    return v;
}
__device__ __forceinline__ unsigned warp_sum_u(unsigned v) {
    #pragma unroll
    for (int o = 16; o > 0; o >>= 1) v += __shfl_down_sync(0xffffffffu, v, o);
    return v;
}
__device__ __forceinline__ double warp_sum_d(double v) {
    #pragma unroll
    for (int o = 16; o > 0; o >>= 1) v += __shfl_down_sync(0xffffffffu, v, o);
    return v;
}

// 3-class focal loss (gamma=2), fast-math transcendentals.
__device__ __forceinline__ float focal3(float l0, float l1, float l2, int lab,
                                        unsigned& valid_cnt) {
    if (lab == IGNORE_LBL) return 0.0f;
    valid_cnt += 1u;
    const float m   = fmaxf(l0, fmaxf(l1, l2));
    const float e0  = __expf(l0 - m);
    const float e1  = __expf(l1 - m);
    const float e2  = __expf(l2 - m);
    const float sum = e0 + e1 + e2;
    const float ey  = (lab == 0) ? e0 : ((lab == 1) ? e1 : e2);
    const float ly  = (lab == 0) ? l0 : ((lab == 1) ? l1 : l2);
    const float ce  = (m + __logf(sum)) - ly;       // lse - l[y]
    const float pt  = __fdividef(ey, sum);          // exp(-ce), exact form
    const float omp = 1.0f - pt;
    return omp * omp * ce;
}

// Numerically-stable BCE-with-logits; arg of log is 1+e, e in (0,1] -> one MUFU.LG2.
__device__ __forceinline__ float bce_logit(float z, float y) {
    return fmaxf(z, 0.0f) - z * y + __logf(1.0f + __expf(-fabsf(z)));
}

__global__ __launch_bounds__(256)
void triple_align_main(const float4* __restrict__ al4,   // aspect logits  [B,S,3] as float4
                       const float4* __restrict__ ol4,   // opinion logits [B,S,3] as float4
                       const float4* __restrict__ bl4,   // boundary logits [B,S,2] as float4
                       const int4*   __restrict__ alab4, // aspect labels  [B,S] as int4
                       const int4*   __restrict__ olab4, // opinion labels [B,S] as int4
                       const int*    __restrict__ alab,  // scalar views for cross-group next
                       const int*    __restrict__ olab)
{
    const int g = blockIdx.x * 256 + threadIdx.x;   // group id: positions 4g..4g+3

    // ---- front-batched wide loads (max MLP) ----
    const float4 A0 = al4[3 * g];
    const float4 A1 = al4[3 * g + 1];
    const float4 A2 = al4[3 * g + 2];
    const float4 O0 = ol4[3 * g];
    const float4 O1 = ol4[3 * g + 1];
    const float4 O2 = ol4[3 * g + 2];
    const float4 Z0 = bl4[2 * g];
    const float4 Z1 = bl4[2 * g + 1];
    const int4   LA = alab4[g];
    const int4   LO = olab4[g];

    // next-labels for last position of the group (batch rows are 8192-aligned, 4 | 8192)
    const int p_next = 4 * g + 4;
    const bool wrap  = ((p_next & (SS - 1)) == 0);
    const int la_n3  = wrap ? -1 : __ldg(&alab[p_next]);
    const int lo_n3  = wrap ? -1 : __ldg(&olab[p_next]);

    float sa = 0.0f, so = 0.0f, sb = 0.0f;
    unsigned ca = 0u, co = 0u;

    // position 0: logits (A0.x A0.y A0.z), next labels LA.y/LO.y
    sa += focal3(A0.x, A0.y, A0.z, LA.x, ca);
    so += focal3(O0.x, O0.y, O0.z, LO.x, co);
    {
        const float y0 = ((LA.x == 1) || (LO.x == 1)) ? 1.0f : 0.0f;
        const float y1 = (((LA.x == 2) && (LA.y != 2)) || ((LO.x == 2) && (LO.y != 2))) ? 1.0f : 0.0f;
        sb += bce_logit(Z0.x, y0) + bce_logit(Z0.y, y1);
    }
    // position 1: (A0.w A1.x A1.y), next LA.z/LO.z
    sa += focal3(A0.w, A1.x, A1.y, LA.y, ca);
    so += focal3(O0.w, O1.x, O1.y, LO.y, co);
    {
        const float y0 = ((LA.y == 1) || (LO.y == 1)) ? 1.0f : 0.0f;
        const float y1 = (((LA.y == 2) && (LA.z != 2)) || ((LO.y == 2) && (LO.z != 2))) ? 1.0f : 0.0f;
        sb += bce_logit(Z0.z, y0) + bce_logit(Z0.w, y1);
    }
    // position 2: (A1.z A1.w A2.x), next LA.w/LO.w
    sa += focal3(A1.z, A1.w, A2.x, LA.z, ca);
    so += focal3(O1.z, O1.w, O2.x, LO.z, co);
    {
        const float y0 = ((LA.z == 1) || (LO.z == 1)) ? 1.0f : 0.0f;
        const float y1 = (((LA.z == 2) && (LA.w != 2)) || ((LO.z == 2) && (LO.w != 2))) ? 1.0f : 0.0f;
        sb += bce_logit(Z1.x, y0) + bce_logit(Z1.y, y1);
    }
    // position 3: (A2.y A2.z A2.w), next la_n3/lo_n3
    sa += focal3(A2.y, A2.z, A2.w, LA.w, ca);
    so += focal3(O2.y, O2.z, O2.w, LO.w, co);
    {
        const float y0 = ((LA.w == 1) || (LO.w == 1)) ? 1.0f : 0.0f;
        const float y1 = (((LA.w == 2) && (la_n3 != 2)) || ((LO.w == 2) && (lo_n3 != 2))) ? 1.0f : 0.0f;
        sb += bce_logit(Z1.z, y0) + bce_logit(Z1.w, y1);
    }

    // ---- block reduction (8 warps) -> per-block slot ----
    __shared__ float    sh_a[8], sh_o[8], sh_b[8];
    __shared__ unsigned sh_ca[8], sh_co[8];
    const int wid = threadIdx.x >> 5;
    const int lid = threadIdx.x & 31;

    sa = warp_sum_f(sa); so = warp_sum_f(so); sb = warp_sum_f(sb);
    ca = warp_sum_u(ca); co = warp_sum_u(co);
    if (lid == 0) { sh_a[wid] = sa; sh_o[wid] = so; sh_b[wid] = sb; sh_ca[wid] = ca; sh_co[wid] = co; }
    __syncthreads();
    if (wid == 0) {
        float va = (lid < 8) ? sh_a[lid] : 0.0f;
        float vo = (lid < 8) ? sh_o[lid] : 0.0f;
        float vb = (lid < 8) ? sh_b[lid] : 0.0f;
        unsigned uca = (lid < 8) ? sh_ca[lid] : 0u;
        unsigned uco = (lid < 8) ? sh_co[lid] : 0u;
        va = warp_sum_f(va); vo = warp_sum_f(vo); vb = warp_sum_f(vb);
        uca = warp_sum_u(uca); uco = warp_sum_u(uco);
        if (lid == 0) {
            d_pa[blockIdx.x] = va;
            d_po[blockIdx.x] = vo;
            d_pb[blockIdx.x] = vb;
            d_ca[blockIdx.x] = uca;
            d_co[blockIdx.x] = uco;
        }
    }
}

__global__ __launch_bounds__(1024)
void finalize_kernel(const float* __restrict__ sl,   // sentiment logits [B,3]
                     const int*   __restrict__ slab, // sentiment labels [B]
                     float* __restrict__ out)
{
    const int t = threadIdx.x;   // 1024 threads; partial arrays are 2048 long

    double va = (double)d_pa[t] + (double)d_pa[t + 1024];
    double vo = (double)d_po[t] + (double)d_po[t + 1024];
    double vb = (double)d_pb[t] + (double)d_pb[t + 1024];
    unsigned uca = d_ca[t] + d_ca[t + 1024];
    unsigned uco = d_co[t] + d_co[t + 1024];

    // sentiment CE: threads 0..255 each handle one batch row
    double vs = 0.0;
    unsigned ucs = 0u;
    if (t < BB) {
        const int lab = slab[t];
        if (lab != IGNORE_LBL) {
            ucs = 1u;
            const float l0 = sl[3 * t + 0];
            const float l1 = sl[3 * t + 1];
            const float l2 = sl[3 * t + 2];
            const float m  = fmaxf(l0, fmaxf(l1, l2));
            const float sum = __expf(l0 - m) + __expf(l1 - m) + __expf(l2 - m);
            const float ly  = (lab == 0) ? l0 : ((lab == 1) ? l1 : l2);
            vs = (double)((m + __logf(sum)) - ly);
        }
    }

    __shared__ double   sd_a[32], sd_o[32], sd_b[32], sd_s[32];
    __shared__ unsigned su_a[32], su_o[32], su_s[32];
    const int wid = t >> 5;
    const int lid = t & 31;

    va = warp_sum_d(va); vo = warp_sum_d(vo); vb = warp_sum_d(vb); vs = warp_sum_d(vs);
    uca = warp_sum_u(uca); uco = warp_sum_u(uco); ucs = warp_sum_u(ucs);
    if (lid == 0) {
        sd_a[wid] = va; sd_o[wid] = vo; sd_b[wid] = vb; sd_s[wid] = vs;
        su_a[wid] = uca; su_o[wid] = uco; su_s[wid] = ucs;
    }
    __syncthreads();
    if (wid == 0) {
        va = sd_a[lid]; vo = sd_o[lid]; vb = sd_b[lid]; vs = sd_s[lid];
        uca = su_a[lid]; uco = su_o[lid]; ucs = su_s[lid];
        va = warp_sum_d(va); vo = warp_sum_d(vo); vb = warp_sum_d(vb); vs = warp_sum_d(vs);
        uca = warp_sum_u(uca); uco = warp_sum_u(uco); ucs = warp_sum_u(ucs);
        if (lid == 0) {
            const float aspect_loss  = (uca > 0) ? (float)(va / (double)(uca < 1u ? 1u : uca)) : 0.0f;
            const float opinion_loss = (uco > 0) ? (float)(vo / (double)(uco < 1u ? 1u : uco)) : 0.0f;
            const float sentiment_loss = (float)(vs / (double)(ucs < 1u ? 1u : ucs));
            const float boundary_loss  = (float)(vb / (double)(NPOS * 2));
            out[0] = aspect_loss + opinion_loss + sentiment_loss + 0.5f * boundary_loss;
        }
    }
}

extern "C" void kernel_launch(void* const* d_in, const int* in_sizes, int n_in,
                              void* d_out, int out_size) {
    const float* aspect_logits    = (const float*)d_in[0];
    const float* opinion_logits   = (const float*)d_in[1];
    const float* sentiment_logits = (const float*)d_in[2];
    const float* boundary_logits  = (const float*)d_in[3];
    const int*   aspect_labels    = (const int*)d_in[4];
    const int*   opinion_labels   = (const int*)d_in[5];
    const int*   sentiment_labels = (const int*)d_in[6];
    float* out = (float*)d_out;

    triple_align_main<<<NBLK, 256>>>(
        (const float4*)aspect_logits, (const float4*)opinion_logits,
        (const float4*)boundary_logits,
        (const int4*)aspect_labels, (const int4*)opinion_labels,
        aspect_labels, opinion_labels);
    finalize_kernel<<<1, 1024>>>(sentiment_logits, sentiment_labels, out);
}